// round 4
// baseline (speedup 1.0000x reference)
#include <cuda_runtime.h>

// ---------------------------------------------------------------------------
// CarryII R4: owner-writes gather via counting-sort CSR (replaces R3's
// linked lists whose dependent pointer-chase regressed).
//   K1: cnt[] = 0
//   K2 x7: cnt[dst]++                         (L2-resident atomics)
//   K3 a/b/c: exclusive scan cnt -> off (and cursor, in place in cnt)
//   K4 x7: pos = cursor[dst]++; src[pos] = s  (CSR fill)
//   K5 x7: row r sums src[off[r]..off[r+1]) feature rows, one __stcs store.
// No zero pass over 1.66GB output, no atomic RFO: each out line written once.
// ---------------------------------------------------------------------------

static constexpr int FEAT_D = 32;
static constexpr int N3C = 1500000;
static constexpr int N4C = 2000000;
static constexpr long long TOT = 2LL * N3C + 5LL * N4C;   // 13,000,000
static constexpr int SCAN_CHUNK = 4096;                    // elems per block
static constexpr int NB = (int)((TOT + SCAN_CHUNK - 1) / SCAN_CHUNK);  // 3174

__device__ int g_cnt[TOT];        // counts -> overwritten with cursor (== off)
__device__ int g_off[TOT + 1];    // stable row offsets
__device__ int g_src[TOT];        // CSR: source node per slot
__device__ int g_bs[NB];
__device__ int g_bs_ex[NB];

__global__ void zero_cnt_kernel() {
    long long i = blockIdx.x * (long long)blockDim.x + threadIdx.x;
    if (i < TOT / 4) ((int4*)g_cnt)[i] = make_int4(0, 0, 0, 0);
}

__global__ void count_kernel(const int* __restrict__ d_idx, int base_row, int n) {
    int e = blockIdx.x * blockDim.x + threadIdx.x;
    if (e < n) atomicAdd(g_cnt + base_row + __ldcs(d_idx + e), 1);
}

// --- scan pass A: per-block (4096 elems) sums -------------------------------
__global__ void scan_block_sum_kernel() {
    __shared__ int sh[256];
    long long base = (long long)blockIdx.x * SCAN_CHUNK;
    int t = threadIdx.x;
    int sum = 0;
    #pragma unroll
    for (int k = 0; k < 16; k++) {
        long long i = base + t + k * 256;           // coalesced
        if (i < TOT) sum += g_cnt[i];
    }
    sh[t] = sum; __syncthreads();
    for (int s = 128; s > 0; s >>= 1) {
        if (t < s) sh[t] += sh[t + s];
        __syncthreads();
    }
    if (t == 0) g_bs[blockIdx.x] = sh[0];
}

// --- scan pass B: single-block exclusive scan of block sums -----------------
__global__ void scan_bs_kernel() {
    __shared__ int sh[1024];
    int t = threadIdx.x;
    int vals[4]; int sum = 0;
    #pragma unroll
    for (int k = 0; k < 4; k++) {
        int i = t * 4 + k;
        vals[k] = (i < NB) ? g_bs[i] : 0;
        sum += vals[k];
    }
    sh[t] = sum; __syncthreads();
    for (int ofs = 1; ofs < 1024; ofs <<= 1) {      // Hillis-Steele inclusive
        int v = (t >= ofs) ? sh[t - ofs] : 0;
        __syncthreads();
        sh[t] += v;
        __syncthreads();
    }
    int run = sh[t] - sum;                          // exclusive prefix of chunk
    #pragma unroll
    for (int k = 0; k < 4; k++) {
        int i = t * 4 + k;
        if (i < NB) g_bs_ex[i] = run;
        run += vals[k];
    }
}

// --- scan pass C: in-block scan, write off + cursor -------------------------
__global__ void scan_fill_off_kernel() {
    __shared__ int sh[256];
    int t = threadIdx.x;
    long long my = (long long)blockIdx.x * SCAN_CHUNK + (long long)t * 16;
    int vals[16]; int sum = 0;
    #pragma unroll
    for (int k = 0; k < 16; k++) {
        long long i = my + k;
        vals[k] = (i < TOT) ? g_cnt[i] : 0;
        sum += vals[k];
    }
    sh[t] = sum; __syncthreads();
    for (int ofs = 1; ofs < 256; ofs <<= 1) {
        int v = (t >= ofs) ? sh[t - ofs] : 0;
        __syncthreads();
        sh[t] += v;
        __syncthreads();
    }
    int run = (sh[t] - sum) + g_bs_ex[blockIdx.x];
    #pragma unroll
    for (int k = 0; k < 16; k++) {
        long long i = my + k;
        if (i < TOT) { g_off[i] = run; g_cnt[i] = run; run += vals[k]; }
    }
    if (my + 16 == TOT) g_off[TOT] = run;           // sentinel (TOT % 16 == 0)
}

__global__ void fill_kernel(const int* __restrict__ s_idx,
                            const int* __restrict__ d_idx,
                            int base_row, int n) {
    int e = blockIdx.x * blockDim.x + threadIdx.x;
    if (e >= n) return;
    int s = __ldcs(s_idx + e);
    int d = __ldcs(d_idx + e);
    int pos = atomicAdd(g_cnt + base_row + d, 1);
    g_src[pos] = s;
}

__global__ void gather_rows_kernel(const float4* __restrict__ feat,
                                   float4* __restrict__ out,
                                   int base_row, int n_rows) {
    long long gid = blockIdx.x * (long long)blockDim.x + threadIdx.x;
    int row = (int)(gid >> 3);                      // 8 lanes per row
    if (row >= n_rows) return;
    int sub = (int)(gid & 7);

    int start = __ldg(g_off + base_row + row);      // coalesced across groups
    int end   = __ldg(g_off + base_row + row + 1);

    float4 acc = make_float4(0.f, 0.f, 0.f, 0.f);
    for (int j = start; j < end; j++) {
        int s = __ldg(g_src + j);                   // contiguous, broadcast
        float4 v = __ldg(feat + (long long)s * 8 + sub);  // 128B line per edge
        acc.x += v.x; acc.y += v.y; acc.z += v.z; acc.w += v.w;
    }
    __stcs(out + (long long)row * 8 + sub, acc);    // single write, evict-first
}

static inline void launch_gather(const float* feat, float* out,
                                 int base_row, int n_rows) {
    long long threads = (long long)n_rows * 8;
    int grid = (int)((threads + 255) / 256);
    gather_rows_kernel<<<grid, 256>>>((const float4*)feat, (float4*)out,
                                      base_row, n_rows);
}

extern "C" void kernel_launch(void* const* d_in, const int* in_sizes, int n_in,
                              void* d_out, int out_size) {
    const float* u2 = (const float*)d_in[0];
    const float* u3 = (const float*)d_in[1];

    const int* s_b0a = (const int*)d_in[2];
    const int* d_b0a = (const int*)d_in[3];
    const int* s_b1a = (const int*)d_in[4];
    const int* d_b1a = (const int*)d_in[5];
    const int* s_b0t = (const int*)d_in[6];
    const int* d_b0t = (const int*)d_in[7];
    const int* s_b1t = (const int*)d_in[8];
    const int* d_b1t = (const int*)d_in[9];
    const int* s_b2t = (const int*)d_in[10];
    const int* d_b2t = (const int*)d_in[11];
    const int* s_a0t = (const int*)d_in[12];
    const int* d_a0t = (const int*)d_in[13];
    const int* s_a1t = (const int*)d_in[14];
    const int* d_a1t = (const int*)d_in[15];

    const int N3 = in_sizes[2];
    const int N4 = in_sizes[6];

    float* out = (float*)d_out;

    int base = 0;
    const int B0 = base; base += N3;
    const int B1 = base; base += N3;
    const int B2 = base; base += N4;
    const int B3 = base; base += N4;
    const int B4 = base; base += N4;
    const int B5 = base; base += N4;
    const int B6 = base;

    // K1: zero counts
    zero_cnt_kernel<<<(int)((TOT / 4 + 255) / 256), 256>>>();

    // K2: count degrees
    count_kernel<<<(N3 + 255) / 256, 256>>>(d_b0a, B0, N3);
    count_kernel<<<(N3 + 255) / 256, 256>>>(d_b1a, B1, N3);
    count_kernel<<<(N4 + 255) / 256, 256>>>(d_b0t, B2, N4);
    count_kernel<<<(N4 + 255) / 256, 256>>>(d_b1t, B3, N4);
    count_kernel<<<(N4 + 255) / 256, 256>>>(d_b2t, B4, N4);
    count_kernel<<<(N4 + 255) / 256, 256>>>(d_a0t, B5, N4);
    count_kernel<<<(N4 + 255) / 256, 256>>>(d_a1t, B6, N4);

    // K3: hierarchical exclusive scan -> g_off (+ cursor in g_cnt)
    scan_block_sum_kernel<<<NB, 256>>>();
    scan_bs_kernel<<<1, 1024>>>();
    scan_fill_off_kernel<<<NB, 256>>>();

    // K4: CSR fill
    fill_kernel<<<(N3 + 255) / 256, 256>>>(s_b0a, d_b0a, B0, N3);
    fill_kernel<<<(N3 + 255) / 256, 256>>>(s_b1a, d_b1a, B1, N3);
    fill_kernel<<<(N4 + 255) / 256, 256>>>(s_b0t, d_b0t, B2, N4);
    fill_kernel<<<(N4 + 255) / 256, 256>>>(s_b1t, d_b1t, B3, N4);
    fill_kernel<<<(N4 + 255) / 256, 256>>>(s_b2t, d_b2t, B4, N4);
    fill_kernel<<<(N4 + 255) / 256, 256>>>(s_a0t, d_a0t, B5, N4);
    fill_kernel<<<(N4 + 255) / 256, 256>>>(s_a1t, d_a1t, B6, N4);

    // K5: owner-writes gather
    launch_gather(u2, out + (long long)B0 * FEAT_D, B0, N3);
    launch_gather(u2, out + (long long)B1 * FEAT_D, B1, N3);
    launch_gather(u2, out + (long long)B2 * FEAT_D, B2, N4);
    launch_gather(u2, out + (long long)B3 * FEAT_D, B3, N4);
    launch_gather(u2, out + (long long)B4 * FEAT_D, B4, N4);
    launch_gather(u3, out + (long long)B5 * FEAT_D, B5, N4);
    launch_gather(u3, out + (long long)B6 * FEAT_D, B6, N4);
}